// round 12
// baseline (speedup 1.0000x reference)
#include <cuda_runtime.h>
#include <math.h>

#define BATCH 8
#define H 1024
#define W 1024
#define NPIX (H * W)

#define TW 128
#define TH 32
#define SW (TW + 2)
#define SH (TH + 2)
#define NTHREADS 256
#define BLOCKS_PER_IMG ((W / TW) * (H / TH))   // 8 * 32 = 256

// Scratch: stencil result t (32 MB, intended L2-resident for pass2),
// per-block partial stats (deterministic slots -> no atomics, graph-replay
// safe), per-batch (mean, invstd).
__device__ float g_t[BATCH * NPIX];
__device__ float g_partial[BATCH * BLOCKS_PER_IMG * 2];
__device__ float g_norm[2 * BATCH];

// ---------------------------------------------------------------------------
// Kernel 1: grayscale -> collapsed LTPE stencil -> t, plus per-block partials.
//   t = 0.5*(g+1) - S/510,  S = sum_j 2^j * neighbor_j, zero-padded borders.
//   j0 (0,-1)=1  j1 (1,-1)=2  j2 (1,0)=4   j3 (1,1)=8
//   j4 (0,1)=16  j5 (-1,1)=32 j6 (-1,0)=64 j7 (-1,-1)=128
// x reads use __ldcs (streaming, read-once) so x doesn't occupy L2 that t needs.
// ---------------------------------------------------------------------------
__global__ __launch_bounds__(NTHREADS) void pass1_kernel(const float* __restrict__ x) {
    __shared__ float sg[SH * SW];

    const int bx = blockIdx.x * TW;
    const int by = blockIdx.y * TH;
    const int b  = blockIdx.z;
    const int tid = threadIdx.x;

    const float* __restrict__ xr = x + (size_t)b * 3 * NPIX;
    const float* __restrict__ xg = xr + NPIX;
    const float* __restrict__ xb = xg + NPIX;

    const bool interior = (bx > 0) && (bx + TW < W) && (by > 0) && (by + TH < H);

    if (interior) {
        // Fast path: no bounds checks; float4 streaming loads (bx % 128 == 0).
        for (int i = tid; i < SH * (TW / 4); i += NTHREADS) {
            int r = i / (TW / 4);
            int c4 = i - r * (TW / 4);
            int o = (by + r - 1) * W + bx + c4 * 4;
            float4 vr = __ldcs((const float4*)(xr + o));
            float4 vg = __ldcs((const float4*)(xg + o));
            float4 vb = __ldcs((const float4*)(xb + o));
            float* d = sg + r * SW + 1 + c4 * 4;
            d[0] = 0.3f * vr.x + 0.59f * vg.x + 0.11f * vb.x;
            d[1] = 0.3f * vr.y + 0.59f * vg.y + 0.11f * vb.y;
            d[2] = 0.3f * vr.z + 0.59f * vg.z + 0.11f * vb.z;
            d[3] = 0.3f * vr.w + 0.59f * vg.w + 0.11f * vb.w;
        }
        // Edge columns: c = 0 (gx = bx-1) and c = SW-1 (gx = bx+TW).
        // These overlap neighboring blocks' tiles -> default (caching) loads.
        for (int i = tid; i < 2 * SH; i += NTHREADS) {
            int r = i >> 1;
            int left = i & 1;
            int o = (by + r - 1) * W + (left ? (bx - 1) : (bx + TW));
            sg[r * SW + (left ? 0 : (SW - 1))] =
                0.3f * xr[o] + 0.59f * xg[o] + 0.11f * xb[o];
        }
    } else {
        // Border path: fully predicated, zero padding outside the image.
        for (int i = tid; i < SH * SW; i += NTHREADS) {
            int r = i / SW;
            int c = i - r * SW;
            int gy = by + r - 1;
            int gx = bx + c - 1;
            float v = 0.0f;
            if (gy >= 0 && gy < H && gx >= 0 && gx < W) {
                int o = gy * W + gx;
                v = 0.3f * xr[o] + 0.59f * xg[o] + 0.11f * xb[o];
            }
            sg[i] = v;
        }
    }
    __syncthreads();

    // Each thread owns column c = tid & 127 in rows r0, r0+2, ... (16 rows of
    // the 32-row tile; two threads per column pair). Hoisted addressing: no
    // div/mod in the hot loop.
    const int c  = tid & (TW - 1);
    const int r0 = (tid >> 7);           // 0 or 1
    float lsum = 0.0f, lsq = 0.0f;
    float* __restrict__ tp = g_t + (size_t)b * NPIX + (size_t)(by + r0) * W + bx + c;

    int s = (r0 + 1) * SW + (c + 1);
    #pragma unroll
    for (int rr = 0; rr < TH / 2; rr++) {
        float S;
        S  =   1.0f * sg[s - 1];
        S +=   2.0f * sg[s + SW - 1];
        S +=   4.0f * sg[s + SW];
        S +=   8.0f * sg[s + SW + 1];
        S +=  16.0f * sg[s + 1];
        S +=  32.0f * sg[s - SW + 1];
        S +=  64.0f * sg[s - SW];
        S += 128.0f * sg[s - SW - 1];
        float t = 0.5f * (sg[s] + 1.0f) - S * (1.0f / 510.0f);
        *tp = t;                          // default write-back: keep in L2
        lsum += t;
        lsq  += t * t;
        s  += 2 * SW;
        tp += 2 * W;
    }

    // Warp shuffle reduction, then cross-warp via smem; deterministic slot write.
    #pragma unroll
    for (int off = 16; off > 0; off >>= 1) {
        lsum += __shfl_xor_sync(0xFFFFFFFFu, lsum, off);
        lsq  += __shfl_xor_sync(0xFFFFFFFFu, lsq,  off);
    }
    __shared__ float rs[NTHREADS / 32], rq[NTHREADS / 32];
    int wid = tid >> 5;
    int lid = tid & 31;
    if (lid == 0) { rs[wid] = lsum; rq[wid] = lsq; }
    __syncthreads();
    if (tid == 0) {
        float s2 = 0.0f, q2 = 0.0f;
        #pragma unroll
        for (int w = 0; w < NTHREADS / 32; w++) { s2 += rs[w]; q2 += rq[w]; }
        int blk = blockIdx.y * gridDim.x + blockIdx.x;    // 0..255 within image
        int slot = (b * BLOCKS_PER_IMG + blk) * 2;
        g_partial[slot]     = s2;
        g_partial[slot + 1] = q2;
    }
}

// ---------------------------------------------------------------------------
// Kernel 2: reduce 256 partials per batch -> mean, invstd (double precision).
// One warp per batch image (population variance, eps = 1e-5).
// ---------------------------------------------------------------------------
__global__ void finalize_kernel() {
    int b   = threadIdx.x >> 5;
    int lid = threadIdx.x & 31;
    if (b >= BATCH) return;

    const float* p = g_partial + b * BLOCKS_PER_IMG * 2;
    double s = 0.0, q = 0.0;
    for (int i = lid; i < BLOCKS_PER_IMG; i += 32) {
        s += (double)p[2 * i];
        q += (double)p[2 * i + 1];
    }
    #pragma unroll
    for (int off = 16; off > 0; off >>= 1) {
        s += __shfl_xor_sync(0xFFFFFFFFu, s, off);
        q += __shfl_xor_sync(0xFFFFFFFFu, q, off);
    }
    if (lid == 0) {
        double n    = (double)NPIX;
        double mean = s / n;
        double var  = q / n - mean * mean;
        g_norm[2 * b]     = (float)mean;
        g_norm[2 * b + 1] = (float)(1.0 / sqrt(var + 1e-5));
    }
}

// ---------------------------------------------------------------------------
// Kernel 3: stream t (L2-resident), normalize, broadcast to 3 channels.
// 2 float4s per thread (front-batched loads -> MLP 2), float4 stores with
// __stcs so the 96 MB write stream doesn't evict t from L2.
// ---------------------------------------------------------------------------
__global__ __launch_bounds__(NTHREADS) void pass2_kernel(float* __restrict__ out) {
    // Each thread handles 2 consecutive float4s = 8 pixels within one batch.
    int idx = (blockIdx.x * NTHREADS + threadIdx.x) * 2;   // float4 index
    int b   = idx >> 18;                                   // NPIX/4 = 2^18
    int pin = (idx & ((NPIX / 4) - 1)) << 2;               // pixel offset

    float mean = g_norm[2 * b];
    float inv  = g_norm[2 * b + 1];

    const float* tb = g_t + (size_t)b * NPIX + pin;
    float4 t0 = *(const float4*)(tb);       // batched: both loads issue
    float4 t1 = *(const float4*)(tb + 4);   // before either store

    float4 o0, o1;
    o0.x = (t0.x - mean) * inv;  o0.y = (t0.y - mean) * inv;
    o0.z = (t0.z - mean) * inv;  o0.w = (t0.w - mean) * inv;
    o1.x = (t1.x - mean) * inv;  o1.y = (t1.y - mean) * inv;
    o1.z = (t1.z - mean) * inv;  o1.w = (t1.w - mean) * inv;

    float* base = out + (size_t)b * 3 * NPIX + pin;
    __stcs((float4*)(base),                o0);
    __stcs((float4*)(base + 4),            o1);
    __stcs((float4*)(base + NPIX),         o0);
    __stcs((float4*)(base + NPIX + 4),     o1);
    __stcs((float4*)(base + 2 * NPIX),     o0);
    __stcs((float4*)(base + 2 * NPIX + 4), o1);
}

// ---------------------------------------------------------------------------
// Launch: 3 graph nodes, no atomics, no persistent mutable state.
// ---------------------------------------------------------------------------
extern "C" void kernel_launch(void* const* d_in, const int* in_sizes, int n_in,
                              void* d_out, int out_size) {
    const float* x = (const float*)d_in[0];
    float* out = (float*)d_out;

    dim3 grid1(W / TW, H / TH, BATCH);   // (8, 32, 8) = 2048 blocks
    pass1_kernel<<<grid1, NTHREADS>>>(x);

    finalize_kernel<<<1, BATCH * 32>>>();

    int n4 = BATCH * NPIX / 8;           // 1M threads, 2 float4s each
    pass2_kernel<<<n4 / NTHREADS, NTHREADS>>>(out);
}

// round 13
// speedup vs baseline: 1.0806x; 1.0806x over previous
#include <cuda_runtime.h>
#include <math.h>

#define BATCH 8
#define H 1024
#define W 1024
#define NPIX (H * W)

#define TW 128
#define TH 32
#define SW 136                 // padded row: 16B-aligned interior at col 4
#define SH (TH + 2)
#define NTHREADS 256
#define BLOCKS_PER_IMG ((W / TW) * (H / TH))   // 8 * 32 = 256

// Scratch: stencil result t (32 MB, L2-resident for pass2), per-block partial
// stats (deterministic slots -> no atomics, graph-replay safe), per-batch
// (mean, invstd).
__device__ float g_t[BATCH * NPIX];
__device__ float g_partial[BATCH * BLOCKS_PER_IMG * 2];
__device__ float g_norm[2 * BATCH];

// ---------------------------------------------------------------------------
// Kernel 1: grayscale -> collapsed LTPE stencil -> t, plus per-block partials.
//   t = 0.5*(g+1) - S/510,  S = sum_j 2^j * neighbor_j, zero-padded borders.
// Uniform path for ALL blocks: float4 body load (always in-bounds) + small
// predicated halo ring. Interior smem columns start at 4 -> STS.128 works.
// ---------------------------------------------------------------------------
__global__ __launch_bounds__(NTHREADS) void pass1_kernel(const float* __restrict__ x) {
    __shared__ float sg[SH * SW];

    const int bx = blockIdx.x * TW;
    const int by = blockIdx.y * TH;
    const int b  = blockIdx.z;
    const int tid = threadIdx.x;

    const float* __restrict__ xr = x + (size_t)b * 3 * NPIX;
    const float* __restrict__ xg = xr + NPIX;
    const float* __restrict__ xb = xg + NPIX;

    // Body: 32 rows x 32 float4 = 1024 vector loads per channel, no predication
    // (the tile body is always inside the image).
    #pragma unroll 2
    for (int i = tid; i < TH * (TW / 4); i += NTHREADS) {
        int r  = i >> 5;             // i / 32
        int c4 = i & 31;
        int o  = (by + r) * W + bx + c4 * 4;
        float4 vr = __ldcs((const float4*)(xr + o));
        float4 vg = __ldcs((const float4*)(xg + o));
        float4 vb = __ldcs((const float4*)(xb + o));
        float4 gy4;
        gy4.x = 0.3f * vr.x + 0.59f * vg.x + 0.11f * vb.x;
        gy4.y = 0.3f * vr.y + 0.59f * vg.y + 0.11f * vb.y;
        gy4.z = 0.3f * vr.z + 0.59f * vg.z + 0.11f * vb.z;
        gy4.w = 0.3f * vr.w + 0.59f * vg.w + 0.11f * vb.w;
        // (r+1)*SW + 4 + c4*4 : SW*4=544 and 4*4=16 bytes -> 16B aligned
        *(float4*)(sg + (r + 1) * SW + 4 + c4 * 4) = gy4;
    }

    // Halo ring: 324 predicated scalar elements (zero outside image).
    //  [0,130)   top row    sr=0,  sc=3+k,   gy=by-1,  gx=bx-1+k
    //  [130,260) bottom row sr=33, sc=3+k,   gy=by+TH, gx=bx-1+k
    //  [260,292) left col   sr=1+k, sc=3,    gy=by+k,  gx=bx-1
    //  [292,324) right col  sr=1+k, sc=132,  gy=by+k,  gx=bx+TW
    for (int i = tid; i < 324; i += NTHREADS) {
        int sr, sc, gy, gx;
        if (i < 260) {
            int k = (i < 130) ? i : i - 130;
            sr = (i < 130) ? 0 : (SH - 1);
            sc = 3 + k;
            gy = (i < 130) ? (by - 1) : (by + TH);
            gx = bx - 1 + k;
        } else if (i < 292) {
            int k = i - 260;
            sr = 1 + k; sc = 3;
            gy = by + k; gx = bx - 1;
        } else {
            int k = i - 292;
            sr = 1 + k; sc = 4 + TW;
            gy = by + k; gx = bx + TW;
        }
        float v = 0.0f;
        if (gy >= 0 && gy < H && gx >= 0 && gx < W) {
            int o = gy * W + gx;
            v = 0.3f * xr[o] + 0.59f * xg[o] + 0.11f * xb[o];
        }
        sg[sr * SW + sc] = v;
    }
    __syncthreads();

    // Stencil weights by offset j (w_j = 2^j):
    //  j0 (0,-1)=1  j1 (1,-1)=2  j2 (1,0)=4   j3 (1,1)=8
    //  j4 (0,1)=16  j5 (-1,1)=32 j6 (-1,0)=64 j7 (-1,-1)=128
    // Each thread owns column c = tid & 127 in rows r0, r0+2, ...
    const int c  = tid & (TW - 1);
    const int r0 = (tid >> 7);           // 0 or 1
    float lsum = 0.0f, lsq = 0.0f;
    float* __restrict__ tp = g_t + (size_t)b * NPIX + (size_t)(by + r0) * W + bx + c;

    int s = (r0 + 1) * SW + (c + 4);
    #pragma unroll
    for (int rr = 0; rr < TH / 2; rr++) {
        float S;
        S  =   1.0f * sg[s - 1];
        S +=   2.0f * sg[s + SW - 1];
        S +=   4.0f * sg[s + SW];
        S +=   8.0f * sg[s + SW + 1];
        S +=  16.0f * sg[s + 1];
        S +=  32.0f * sg[s - SW + 1];
        S +=  64.0f * sg[s - SW];
        S += 128.0f * sg[s - SW - 1];
        float t = 0.5f * (sg[s] + 1.0f) - S * (1.0f / 510.0f);
        *tp = t;                          // default write-back: keep in L2
        lsum += t;
        lsq  += t * t;
        s  += 2 * SW;
        tp += 2 * W;
    }

    // Warp shuffle reduction, then cross-warp via smem; deterministic slot write.
    #pragma unroll
    for (int off = 16; off > 0; off >>= 1) {
        lsum += __shfl_xor_sync(0xFFFFFFFFu, lsum, off);
        lsq  += __shfl_xor_sync(0xFFFFFFFFu, lsq,  off);
    }
    __shared__ float rs[NTHREADS / 32], rq[NTHREADS / 32];
    int wid = tid >> 5;
    int lid = tid & 31;
    if (lid == 0) { rs[wid] = lsum; rq[wid] = lsq; }
    __syncthreads();
    if (tid == 0) {
        float s2 = 0.0f, q2 = 0.0f;
        #pragma unroll
        for (int w = 0; w < NTHREADS / 32; w++) { s2 += rs[w]; q2 += rq[w]; }
        int blk = blockIdx.y * gridDim.x + blockIdx.x;    // 0..255 within image
        int slot = (b * BLOCKS_PER_IMG + blk) * 2;
        g_partial[slot]     = s2;
        g_partial[slot + 1] = q2;
    }
}

// ---------------------------------------------------------------------------
// Kernel 2: reduce 256 partials per batch -> mean, invstd (double precision).
// One warp per batch image (population variance, eps = 1e-5).
// ---------------------------------------------------------------------------
__global__ void finalize_kernel() {
    int b   = threadIdx.x >> 5;
    int lid = threadIdx.x & 31;
    if (b >= BATCH) return;

    const float* p = g_partial + b * BLOCKS_PER_IMG * 2;
    double s = 0.0, q = 0.0;
    for (int i = lid; i < BLOCKS_PER_IMG; i += 32) {
        s += (double)p[2 * i];
        q += (double)p[2 * i + 1];
    }
    #pragma unroll
    for (int off = 16; off > 0; off >>= 1) {
        s += __shfl_xor_sync(0xFFFFFFFFu, s, off);
        q += __shfl_xor_sync(0xFFFFFFFFu, q, off);
    }
    if (lid == 0) {
        double n    = (double)NPIX;
        double mean = s / n;
        double var  = q / n - mean * mean;
        g_norm[2 * b]     = (float)mean;
        g_norm[2 * b + 1] = (float)(1.0 / sqrt(var + 1e-5));
    }
}

// ---------------------------------------------------------------------------
// Kernel 3: stream t (L2-resident), normalize, broadcast to 3 channels.
// 4 float4s per thread (front-batched loads -> MLP 4) to cover L2/DRAM
// latency; __stcs stores so the 96 MB write stream doesn't evict t from L2.
// ---------------------------------------------------------------------------
__global__ __launch_bounds__(NTHREADS) void pass2_kernel(float* __restrict__ out) {
    // Each thread handles 4 consecutive float4s = 16 pixels within one batch.
    int idx = (blockIdx.x * NTHREADS + threadIdx.x) * 4;   // float4 index
    int b   = idx >> 18;                                   // NPIX/4 = 2^18
    int pin = (idx & ((NPIX / 4) - 1)) << 2;               // pixel offset

    float mean = g_norm[2 * b];
    float inv  = g_norm[2 * b + 1];

    const float* tb = g_t + (size_t)b * NPIX + pin;
    float4 t0 = *(const float4*)(tb);        // 4 loads batched before any store
    float4 t1 = *(const float4*)(tb + 4);
    float4 t2 = *(const float4*)(tb + 8);
    float4 t3 = *(const float4*)(tb + 12);

    float4 o0, o1, o2, o3;
    o0.x = (t0.x - mean) * inv;  o0.y = (t0.y - mean) * inv;
    o0.z = (t0.z - mean) * inv;  o0.w = (t0.w - mean) * inv;
    o1.x = (t1.x - mean) * inv;  o1.y = (t1.y - mean) * inv;
    o1.z = (t1.z - mean) * inv;  o1.w = (t1.w - mean) * inv;
    o2.x = (t2.x - mean) * inv;  o2.y = (t2.y - mean) * inv;
    o2.z = (t2.z - mean) * inv;  o2.w = (t2.w - mean) * inv;
    o3.x = (t3.x - mean) * inv;  o3.y = (t3.y - mean) * inv;
    o3.z = (t3.z - mean) * inv;  o3.w = (t3.w - mean) * inv;

    float* base = out + (size_t)b * 3 * NPIX + pin;
    __stcs((float4*)(base),                 o0);
    __stcs((float4*)(base + 4),             o1);
    __stcs((float4*)(base + 8),             o2);
    __stcs((float4*)(base + 12),            o3);
    __stcs((float4*)(base + NPIX),          o0);
    __stcs((float4*)(base + NPIX + 4),      o1);
    __stcs((float4*)(base + NPIX + 8),      o2);
    __stcs((float4*)(base + NPIX + 12),     o3);
    __stcs((float4*)(base + 2 * NPIX),      o0);
    __stcs((float4*)(base + 2 * NPIX + 4),  o1);
    __stcs((float4*)(base + 2 * NPIX + 8),  o2);
    __stcs((float4*)(base + 2 * NPIX + 12), o3);
}

// ---------------------------------------------------------------------------
// Launch: 3 graph nodes, no atomics, no persistent mutable state.
// ---------------------------------------------------------------------------
extern "C" void kernel_launch(void* const* d_in, const int* in_sizes, int n_in,
                              void* d_out, int out_size) {
    const float* x = (const float*)d_in[0];
    float* out = (float*)d_out;

    dim3 grid1(W / TW, H / TH, BATCH);   // (8, 32, 8) = 2048 blocks
    pass1_kernel<<<grid1, NTHREADS>>>(x);

    finalize_kernel<<<1, BATCH * 32>>>();

    int n4 = BATCH * NPIX / 16;          // 512K threads, 4 float4s each
    pass2_kernel<<<n4 / NTHREADS, NTHREADS>>>(out);
}